// round 1
// baseline (speedup 1.0000x reference)
#include <cuda_runtime.h>

// Problem: L_spa loss.
// org, enhance: [32, 3, 512, 512] float32.
// d[b,ph,pw] = (sum_{c,4x4 block} (org - enh)) / 48   -> [32,128,128]
// loss = mean over (b,ph,pw) of sum of 4 shift-diff squares (zero-padded
// neighbors: out-of-range neighbor term contributes d^2).

#define B     32
#define HW    512
#define PH    128            // pooled H/W
#define NPIX  (B * PH * PH)  // 524288 pooled pixels

// scratch: pooled diff buffer (2 MB), device global (no allocations allowed)
__device__ float g_diff[NPIX];

__global__ void zero_out_kernel(float* out) { out[0] = 0.0f; }

// Kernel 1: fused channel-mean + 4x4 avgpool of (org - enh).
// One thread per pooled pixel; 24 float4 loads (3 ch x 2 tensors x 4 rows),
// consecutive threads -> consecutive float4 addresses (fully coalesced).
__global__ void __launch_bounds__(256) pool_diff_kernel(
    const float4* __restrict__ org, const float4* __restrict__ enh) {
    int i = blockIdx.x * blockDim.x + threadIdx.x;   // exact grid, no guard needed
    int b  = i >> 14;
    int ph = (i >> 7) & 127;
    int pw = i & 127;

    // addressing in float4 units: one 512-wide row = 128 float4
    const int ROW4 = HW / 4;                 // 128
    const int CH4  = HW * ROW4;              // 512*128 float4 per channel
    int base = b * 3 * CH4 + (ph * 4) * ROW4 + pw;

    float s = 0.0f;
#pragma unroll
    for (int c = 0; c < 3; c++) {
#pragma unroll
        for (int dy = 0; dy < 4; dy++) {
            float4 o = __ldg(&org[base + c * CH4 + dy * ROW4]);
            float4 e = __ldg(&enh[base + c * CH4 + dy * ROW4]);
            s += (o.x - e.x) + (o.y - e.y) + (o.z - e.z) + (o.w - e.w);
        }
    }
    g_diff[i] = s * (1.0f / 48.0f);
}

// Kernel 2: shift-difference loss + reduction. diff buffer is 2 MB -> L2 hit.
__global__ void __launch_bounds__(256) spa_loss_kernel(float* __restrict__ out) {
    int i = blockIdx.x * blockDim.x + threadIdx.x;
    int b  = i >> 14;
    int ph = (i >> 7) & 127;
    int pw = i & 127;

    const float* d = g_diff + (b << 14);
    int idx = (ph << 7) + pw;
    float c = d[idx];
    float l = (pw > 0)      ? d[idx - 1]   : 0.0f;
    float r = (pw < 127)    ? d[idx + 1]   : 0.0f;
    float u = (ph > 0)      ? d[idx - 128] : 0.0f;
    float dn = (ph < 127)   ? d[idx + 128] : 0.0f;

    float t = (c - l) * (c - l) + (c - r) * (c - r)
            + (c - u) * (c - u) + (c - dn) * (c - dn);

    // warp reduce
#pragma unroll
    for (int off = 16; off > 0; off >>= 1)
        t += __shfl_down_sync(0xFFFFFFFFu, t, off);

    __shared__ float warp_sums[8];   // 256 threads / 32
    int lane = threadIdx.x & 31;
    int wid  = threadIdx.x >> 5;
    if (lane == 0) warp_sums[wid] = t;
    __syncthreads();

    if (wid == 0) {
        float v = (lane < 8) ? warp_sums[lane] : 0.0f;
#pragma unroll
        for (int off = 4; off > 0; off >>= 1)
            v += __shfl_down_sync(0xFFFFFFFFu, v, off);
        if (lane == 0)
            atomicAdd(out, v * (1.0f / (float)NPIX));
    }
}

extern "C" void kernel_launch(void* const* d_in, const int* in_sizes, int n_in,
                              void* d_out, int out_size) {
    const float4* org = (const float4*)d_in[0];
    const float4* enh = (const float4*)d_in[1];
    float* out = (float*)d_out;

    zero_out_kernel<<<1, 1>>>(out);
    pool_diff_kernel<<<NPIX / 256, 256>>>(org, enh);
    spa_loss_kernel<<<NPIX / 256, 256>>>(out);
}

// round 2
// speedup vs baseline: 1.1170x; 1.1170x over previous
#include <cuda_runtime.h>

// L_spa loss, fully fused single kernel.
// org, enhance: [32, 3, 512, 512] fp32.
// d[b,ph,pw] = (sum over 3ch x 4x4 block of (org-enh)) / 48   [32,128,128]
// loss = mean over pixels of sum of 4 shift-diff squares (zero padding).
//
// One block = one 32-row pooled band of one image (grid 4 bands x 32 batch).
// Block recomputes 2 halo rows (top/bottom) so the shift loss is resolved
// entirely from shared memory. Final scalar via last-block reduction
// (threadfence + counter, counter self-resets for graph replay determinism).

#define HWROW4   128                 // 512-float raw row = 128 float4
#define CH4      (512 * HWROW4)     // float4 per channel = 65536
#define IMG4     (3 * CH4)          // float4 per image
#define PH       128                 // pooled H = W
#define BAND     32                  // pooled rows per block
#define TROWS    (BAND + 2)          // with halo
#define NPIX     (32 * PH * PH)     // 524288
#define NBLOCKS  (4 * 32)

__device__ float    g_acc;     // zero-initialized; last block resets it
__device__ unsigned g_count;   // zero-initialized; last block resets it

__global__ void __launch_bounds__(1024, 1) spa_fused_kernel(
    const float4* __restrict__ org, const float4* __restrict__ enh,
    float* __restrict__ out) {
    __shared__ float tile[TROWS][PH];      // 17408 B
    __shared__ float warp_sums[32];

    const int band = blockIdx.x;           // 0..3
    const int b    = blockIdx.y;           // 0..31
    const int tid  = threadIdx.x;
    const int ibase = b * IMG4;

    // ---- Phase 1: pool (org - enh) into tile, rows band*32-1 .. band*32+32
    for (int i = tid; i < TROWS * PH; i += 1024) {
        int r   = i >> 7;                  // 0..33 (tile row)
        int pw  = i & 127;
        int gph = band * BAND + r - 1;     // global pooled row
        float v = 0.0f;
        if (gph >= 0 && gph < PH) {
            int base = ibase + (gph * 4) * HWROW4 + pw;
            float s = 0.0f;
#pragma unroll
            for (int c = 0; c < 3; c++) {
#pragma unroll
                for (int dy = 0; dy < 4; dy++) {
                    float4 o = __ldg(&org[base + c * CH4 + dy * HWROW4]);
                    float4 e = __ldg(&enh[base + c * CH4 + dy * HWROW4]);
                    s += (o.x - e.x) + (o.y - e.y) + (o.z - e.z) + (o.w - e.w);
                }
            }
            v = s * (1.0f / 48.0f);
        }
        tile[r][pw] = v;
    }
    __syncthreads();

    // ---- Phase 2: shift-difference loss over the 32 interior rows
    float t = 0.0f;
#pragma unroll
    for (int k = 0; k < (BAND * PH) / 1024; k++) {
        int i  = k * 1024 + tid;
        int r  = (i >> 7) + 1;             // 1..32
        int pw = i & 127;
        float c  = tile[r][pw];
        float l  = (pw > 0)        ? tile[r][pw - 1] : 0.0f;
        float rr = (pw < PH - 1)   ? tile[r][pw + 1] : 0.0f;
        float u  = tile[r - 1][pw];        // halo handles image edge (=0)
        float dn = tile[r + 1][pw];
        t += (c - l) * (c - l) + (c - rr) * (c - rr)
           + (c - u) * (c - u) + (c - dn) * (c - dn);
    }

    // ---- Phase 3: block reduce
#pragma unroll
    for (int off = 16; off > 0; off >>= 1)
        t += __shfl_down_sync(0xFFFFFFFFu, t, off);
    int lane = tid & 31, wid = tid >> 5;
    if (lane == 0) warp_sums[wid] = t;
    __syncthreads();
    if (wid == 0) {
        float v = warp_sums[lane];
#pragma unroll
        for (int off = 16; off > 0; off >>= 1)
            v += __shfl_down_sync(0xFFFFFFFFu, v, off);
        if (lane == 0) {
            atomicAdd(&g_acc, v);
            __threadfence();
            unsigned done = atomicAdd(&g_count, 1u);
            if (done == NBLOCKS - 1) {
                // last block: finalize and reset for next graph replay
                out[0] = g_acc * (1.0f / (float)NPIX);
                g_acc   = 0.0f;
                g_count = 0u;
            }
        }
    }
}

extern "C" void kernel_launch(void* const* d_in, const int* in_sizes, int n_in,
                              void* d_out, int out_size) {
    const float4* org = (const float4*)d_in[0];
    const float4* enh = (const float4*)d_in[1];
    float* out = (float*)d_out;
    spa_fused_kernel<<<dim3(4, 32), 1024>>>(org, enh, out);
}